// round 16
// baseline (speedup 1.0000x reference)
#include <cuda_runtime.h>
#include <cuda_fp16.h>
#include <math.h>
#include <cstdint>

#define SEQ 2048
#define DM 1024
#define NH 16
#define HD 64
#define NB 2
#define MROWS (NB * SEQ)   // 4096
#define N3 (3 * DM)        // 3072 (qkv buffer width)

// Q projection pre-scaled by 0.125*log2(e): softmax runs in exp2 domain.
#define QSCALE 0.18033688011112042f

// Scratch (__device__ globals; allocation-free rule).
__device__ __half g_inh[3 * MROWS * DM];  // fp16(q|k|v) inputs, tensor-major
__device__ __half g_wT[4 * DM * DM];      // fp16(Wq^T|Wk^T|Wv^T|Wo^T) [N][K]
__device__ __half g_qkv[MROWS * N3];      // fp16 proj: [token][Q|Kc|.]
__device__ __half g_vwT[NB * DM * SEQ];   // fp16(proj V)^T compacted [b][c][j]
__device__ __half g_ctx[MROWS * DM];      // fp16(attn out)  [token][c]
__device__ int    g_idx[NB * SEQ];        // compacted key token index (local)
__device__ int    g_mkc[NB * SEQ];        // compacted mask (1 valid, 0 pad)
__device__ int    g_ntc[NB];              // #64-key tiles per batch

__device__ __forceinline__ void mma_f16(float c[4], const unsigned a[4],
                                        const unsigned b[2]) {
    asm volatile(
        "mma.sync.aligned.m16n8k16.row.col.f32.f16.f16.f32 "
        "{%0,%1,%2,%3}, {%4,%5,%6,%7}, {%8,%9}, {%0,%1,%2,%3};\n"
        : "+f"(c[0]), "+f"(c[1]), "+f"(c[2]), "+f"(c[3])
        : "r"(a[0]), "r"(a[1]), "r"(a[2]), "r"(a[3]), "r"(b[0]), "r"(b[1]));
}

// ldmatrix x4: four 8x8 b16 fragments in one instruction.
__device__ __forceinline__ void ldm4(unsigned& r0, unsigned& r1,
                                     unsigned& r2, unsigned& r3,
                                     const __half* p) {
    unsigned a = (unsigned)__cvta_generic_to_shared(p);
    asm volatile("ldmatrix.sync.aligned.m8n8.x4.shared.b16 {%0,%1,%2,%3}, [%4];"
                 : "=r"(r0), "=r"(r1), "=r"(r2), "=r"(r3) : "r"(a));
}

__device__ __forceinline__ unsigned h2ex2(float lo, float hi) {
    __half2 d = __floats2half2_rn(lo, hi);
    unsigned x = *(unsigned*)&d, r;
    asm("ex2.approx.f16x2 %0, %1;" : "=r"(r) : "r"(x));
    return r;
}
__device__ __forceinline__ float ex2f(float x) {
    float r;
    asm("ex2.approx.f32 %0, %1;" : "=f"(r) : "f"(x));
    return r;
}

__device__ __forceinline__ void cp_cg16(void* dst, const void* src) {
    unsigned u = (unsigned)__cvta_generic_to_shared(dst);
    asm volatile("cp.async.cg.shared.global [%0], [%1], 16;" :: "r"(u), "l"(src));
}

extern __shared__ float sm_dyn[];

// ---------------------------------------------------------------------------
// Prepass kernels.
// ---------------------------------------------------------------------------
__global__ __launch_bounds__(256) void to_f16_3(
    const float4* __restrict__ q, const float4* __restrict__ k,
    const float4* __restrict__ v, __half2* __restrict__ out, int n4)
{
    int i = blockIdx.x * 256 + threadIdx.x;
    const float4* in = (blockIdx.z == 0) ? q : (blockIdx.z == 1) ? k : v;
    __half2* o = out + (size_t)blockIdx.z * (2 * (size_t)n4);
    if (i < n4) {
        float4 x = in[i];
        o[2 * i]     = __floats2half2_rn(x.x, x.y);
        o[2 * i + 1] = __floats2half2_rn(x.z, x.w);
    }
}

__global__ __launch_bounds__(256) void transp_w4(
    const float* __restrict__ w0, const float* __restrict__ w1,
    const float* __restrict__ w2, const float* __restrict__ w3,
    __half* __restrict__ out)
{
    __shared__ float t[32][33];
    const float* in = (blockIdx.z == 0) ? w0 : (blockIdx.z == 1) ? w1
                    : (blockIdx.z == 2) ? w2 : w3;
    __half* o = out + (size_t)blockIdx.z * DM * DM;
    int tx = threadIdx.x, ty = threadIdx.y;           // 32 x 8
    int bx = blockIdx.x * 32, by = blockIdx.y * 32;
#pragma unroll
    for (int j = 0; j < 4; j++)
        t[ty + j * 8][tx] = in[(size_t)(by + ty + j * 8) * DM + bx + tx];
    __syncthreads();
#pragma unroll
    for (int j = 0; j < 4; j++)
        o[(size_t)(bx + ty + j * 8) * DM + by + tx] =
            __float2half_rn(t[tx][ty + j * 8]);
}

// Order-preserving key compaction (masked keys have exactly 0 weight).
__global__ __launch_bounds__(1024) void compact_mask(
    const int* __restrict__ vmask, int* __restrict__ idx,
    int* __restrict__ mkc, int* __restrict__ ntc)
{
    __shared__ int s[1024];
    __shared__ int cnt_s;
    const int b = blockIdx.x, t = threadIdx.x;
    const int* mb = vmask + b * SEQ;
    const int m0 = mb[2 * t] ? 1 : 0;
    const int m1 = mb[2 * t + 1] ? 1 : 0;
    const int p = m0 + m1;
    s[t] = p;
    __syncthreads();
    for (int off = 1; off < 1024; off <<= 1) {
        int v = s[t];
        if (t >= off) v += s[t - off];
        __syncthreads();
        s[t] = v;
        __syncthreads();
    }
    const int incl = s[t];
    if (t == 1023) cnt_s = incl;
    __syncthreads();
    const int cnt = cnt_s;
    idx[b * SEQ + t] = 0;
    idx[b * SEQ + t + 1024] = 0;
    mkc[b * SEQ + t] = (t < cnt) ? 1 : 0;
    mkc[b * SEQ + t + 1024] = (t + 1024 < cnt) ? 1 : 0;
    __syncthreads();
    const int e = incl - p;
    if (m0) idx[b * SEQ + e] = 2 * t;
    if (m1) idx[b * SEQ + e + m0] = 2 * t + 1;
    if (t == 0) ntc[b] = (cnt + 63) >> 6;
}

// ---------------------------------------------------------------------------
// GEMM tiles: 128x128 block, 256 threads, 8 warps x (64x32), m16n8k16,
// k-chunk 64 halves, 3-stage cp.async, pitch 36 words (72 halves).
// Fragments via ldmatrix.x4 (conflict-free: bank = 4r mod 32 per phase).
// ---------------------------------------------------------------------------
#define GW 36
#define GEMM_STAGE (128 * GW)
#define GEMM_NSTG 3
#define GEMM_SMEM ((2 * GEMM_NSTG * GEMM_STAGE) * (int)sizeof(float))  // 110592

__device__ __forceinline__ void gemm_prefetch(
    unsigned* As, unsigned* Bs, const __half* A, const __half* WT,
    const int* __restrict__ stok,
    int K, int bn, int k0, int tid)
{
#pragma unroll
    for (int j = 0; j < 4; j++) {
        int idx = tid + j * 256;
        int row = idx >> 3;
        int c16 = idx & 7;
        cp_cg16(&As[row * GW + c16 * 4],
                A + (size_t)stok[row] * K + k0 + c16 * 8);
        cp_cg16(&Bs[row * GW + c16 * 4],
                WT + (size_t)(bn + row) * K + k0 + c16 * 8);
    }
}

__device__ __forceinline__ void gemm_mainloop(
    float acc[4][4][4], const __half* A, const __half* WT,
    const int* __restrict__ stok,
    int K, int bn, int tid, int wm, int wn)
{
    unsigned* As0 = (unsigned*)sm_dyn;
    unsigned* Bs0 = As0 + GEMM_NSTG * GEMM_STAGE;
    const int lane = tid & 31;
    const int rl = lane & 15;            // ldmatrix row-in-tile
    const int ch = (lane >> 4) * 8;      // ldmatrix col-half offset

    gemm_prefetch(As0, Bs0, A, WT, stok, K, bn, 0, tid);
    asm volatile("cp.async.commit_group;" ::: "memory");
    gemm_prefetch(As0 + GEMM_STAGE, Bs0 + GEMM_STAGE, A, WT, stok, K, bn, 64, tid);
    asm volatile("cp.async.commit_group;" ::: "memory");

    const int NKI = K / 64;
    for (int i = 0; i < NKI; i++) {
        asm volatile("cp.async.wait_group 1;" ::: "memory");
        __syncthreads();
        int pf = i + 2;
        if (pf < NKI) {
            int j = pf % GEMM_NSTG;
            gemm_prefetch(As0 + j * GEMM_STAGE, Bs0 + j * GEMM_STAGE,
                          A, WT, stok, K, bn, pf * 64, tid);
        }
        asm volatile("cp.async.commit_group;" ::: "memory");
        const int st = i % GEMM_NSTG;
        const __half* Ah = (const __half*)(As0 + st * GEMM_STAGE);
        const __half* Bh = (const __half*)(Bs0 + st * GEMM_STAGE);

#pragma unroll
        for (int kf = 0; kf < 4; kf++) {
            unsigned af[4][4], bf[4][2];
#pragma unroll
            for (int mi = 0; mi < 4; mi++)
                ldm4(af[mi][0], af[mi][1], af[mi][2], af[mi][3],
                     Ah + (wm + mi * 16 + rl) * 72 + kf * 16 + ch);
#pragma unroll
            for (int nj = 0; nj < 2; nj++) {
                unsigned r0, r1, r2, r3;
                ldm4(r0, r1, r2, r3,
                     Bh + (wn + nj * 16 + rl) * 72 + kf * 16 + ch);
                bf[2 * nj][0] = r0; bf[2 * nj + 1][0] = r1;
                bf[2 * nj][1] = r2; bf[2 * nj + 1][1] = r3;
            }
#pragma unroll
            for (int mi = 0; mi < 4; mi++)
#pragma unroll
                for (int ni = 0; ni < 4; ni++)
                    mma_f16(acc[mi][ni], af[mi], bf[ni]);
        }
    }
}

// Grouped QKV projection. z=0: Q (scaled), all tokens. z=1: K compacted.
// z=2: V compacted -> vwT[b][c][j] transposed via smem restage.
__global__ __launch_bounds__(256, 2) void gemm_qkv(
    const __half* __restrict__ inh, const __half* __restrict__ wT,
    const float* __restrict__ bq, const float* __restrict__ bk,
    const float* __restrict__ bv, __half* __restrict__ qkv,
    __half* __restrict__ vwT,
    const int* __restrict__ idx, const int* __restrict__ ntc)
{
    __shared__ int stok[128];

    const int tid  = threadIdx.x;
    const int lane = tid & 31;
    const int warp = tid >> 5;
    const int g = lane >> 2, t = lane & 3;
    const int wm = (warp >> 2) * 64;
    const int wn = (warp & 3) * 32;
    const int bm = blockIdx.y * 128;
    const int bn = blockIdx.x * 128;
    const int z  = blockIdx.z;
    const int b  = bm >> 11;
    const int lm = bm & 2047;

    if (z > 0 && lm >= ntc[b] * 64) return;

    if (tid < 128)
        stok[tid] = (z == 0) ? (bm + tid)
                             : (b * SEQ + idx[b * SEQ + lm + tid]);
    __syncthreads();

    const __half* A  = inh + (size_t)z * MROWS * DM;
    const __half* WT = wT  + (size_t)z * DM * DM;
    const float* bias = (z == 0) ? bq : (z == 1) ? bk : bv;
    const float sc = (z == 0) ? QSCALE : 1.0f;

    float acc[4][4][4];
#pragma unroll
    for (int mi = 0; mi < 4; mi++)
#pragma unroll
        for (int ni = 0; ni < 4; ni++)
#pragma unroll
            for (int e = 0; e < 4; e++) acc[mi][ni][e] = 0.0f;

    gemm_mainloop(acc, A, WT, stok, DM, bn, tid, wm, wn);

    if (z < 2) {
#pragma unroll
        for (int mi = 0; mi < 4; mi++) {
            int r0 = bm + wm + mi * 16 + g;
#pragma unroll
            for (int ni = 0; ni < 4; ni++) {
                int cb = bn + wn + ni * 8 + 2 * t;
                float b0 = bias[cb], b1 = bias[cb + 1];
                float x00 = (acc[mi][ni][0] + b0) * sc;
                float x01 = (acc[mi][ni][1] + b1) * sc;
                float x10 = (acc[mi][ni][2] + b0) * sc;
                float x11 = (acc[mi][ni][3] + b1) * sc;
                __half* c0p = qkv + (size_t)r0 * N3 + z * DM + cb;
                *(__half2*)c0p = __floats2half2_rn(x00, x01);
                *(__half2*)(c0p + (size_t)8 * N3) = __floats2half2_rn(x10, x11);
            }
        }
    } else {
        __syncthreads();
        __half* ts = (__half*)sm_dyn;   // [128 c][136 tok-pitch]
#pragma unroll
        for (int mi = 0; mi < 4; mi++) {
            int tokl = wm + mi * 16 + g;
#pragma unroll
            for (int ni = 0; ni < 4; ni++) {
                int cl = wn + ni * 8 + 2 * t;
                float b0 = bias[bn + cl], b1 = bias[bn + cl + 1];
                ts[cl * 136 + tokl]           = __float2half_rn(acc[mi][ni][0] + b0);
                ts[(cl + 1) * 136 + tokl]     = __float2half_rn(acc[mi][ni][1] + b1);
                ts[cl * 136 + tokl + 8]       = __float2half_rn(acc[mi][ni][2] + b0);
                ts[(cl + 1) * 136 + tokl + 8] = __float2half_rn(acc[mi][ni][3] + b1);
            }
        }
        __syncthreads();
#pragma unroll
        for (int it = 0; it < 8; it++) {
            int idx2 = tid + it * 256;
            int cl = idx2 >> 4;
            int tk = (idx2 & 15) * 8;
            uint4 y = *(const uint4*)&ts[cl * 136 + tk];
            *(uint4*)&vwT[((size_t)b * DM + bn + cl) * SEQ + lm + tk] = y;
        }
    }
}

// Output projection: C(fp32) = ctx(fp16) @ Wo + bo.
__global__ __launch_bounds__(256, 2) void gemm_out(
    const __half* __restrict__ A, const __half* __restrict__ WT,
    const float* __restrict__ bias, float* __restrict__ C)
{
    __shared__ int stok[128];

    const int tid  = threadIdx.x;
    const int lane = tid & 31;
    const int warp = tid >> 5;
    const int g = lane >> 2, t = lane & 3;
    const int wm = (warp >> 2) * 64;
    const int wn = (warp & 3) * 32;
    const int bm = blockIdx.y * 128;
    const int bn = blockIdx.x * 128;

    if (tid < 128) stok[tid] = bm + tid;
    __syncthreads();

    float acc[4][4][4];
#pragma unroll
    for (int mi = 0; mi < 4; mi++)
#pragma unroll
        for (int ni = 0; ni < 4; ni++)
#pragma unroll
            for (int e = 0; e < 4; e++) acc[mi][ni][e] = 0.0f;

    gemm_mainloop(acc, A, WT, stok, DM, bn, tid, wm, wn);

#pragma unroll
    for (int mi = 0; mi < 4; mi++) {
        int r0 = bm + wm + mi * 16 + g;
#pragma unroll
        for (int ni = 0; ni < 4; ni++) {
            int cb = bn + wn + ni * 8 + 2 * t;
            float b0 = bias[cb], b1 = bias[cb + 1];
            *(float2*)&C[(size_t)r0 * DM + cb] =
                make_float2(acc[mi][ni][0] + b0, acc[mi][ni][1] + b1);
            *(float2*)&C[(size_t)(r0 + 8) * DM + cb] =
                make_float2(acc[mi][ni][2] + b0, acc[mi][ni][3] + b1);
        }
    }
}

// ---------------------------------------------------------------------------
// Flash-attention over COMPACTED keys. fp16 mma + ldmatrix fragments,
// exp2 softmax (f16x2), ones-column l. 128 thr / 4 warps, QROWS=128,
// 3 CTAs/SM.
// ---------------------------------------------------------------------------
#define QROWS 128
#define KTILE 64
#define NSTG 3
#define AT_W 36
#define STAGE_W (KTILE * AT_W * 2 + 64)
#define QS_W (QROWS * AT_W)
#define ATTN_SMEM ((NSTG * STAGE_W + QS_W) * (int)sizeof(float))  // 74496
#define ONES_H2 0x3C003C00u

__device__ __forceinline__ void attn_prefetch(
    unsigned* stage, const __half* kb, const __half* vtb, const int* mb,
    int kt, int tid)
{
    unsigned* Ks  = stage;
    unsigned* VTs = stage + KTILE * AT_W;
    unsigned* Mk  = VTs + KTILE * AT_W;
#pragma unroll
    for (int j = 0; j < 4; j++) {
        int idx = tid + j * 128;
        int row = idx >> 3;
        int c16 = idx & 7;
        cp_cg16(&Ks[row * AT_W + c16 * 4],
                kb + (size_t)(kt * KTILE + row) * N3 + c16 * 8);
        cp_cg16(&VTs[row * AT_W + c16 * 4],
                vtb + (size_t)row * SEQ + kt * KTILE + c16 * 8);
    }
    if (tid < 16) cp_cg16(&Mk[tid * 4], mb + kt * KTILE + tid * 4);
}

__global__ __launch_bounds__(128, 3) void attn_mma(
    const __half* __restrict__ qkv, const __half* __restrict__ vwT,
    const int* __restrict__ mkc, const int* __restrict__ ntc,
    __half* __restrict__ ctx)
{
    const int tid  = threadIdx.x;
    const int lane = tid & 31;
    const int warp = tid >> 5;
    const int g = lane >> 2, t = lane & 3;
    const int rl = lane & 15;
    const int ch = (lane >> 4) * 8;
    const int qrow0 = warp * 32;
    const int qt = blockIdx.x, h = blockIdx.y, b = blockIdx.z;
    const int nt = ntc[b];

    unsigned* Qs = (unsigned*)(sm_dyn + NSTG * STAGE_W);
    const __half* Qh = (const __half*)Qs;

    const __half* qb = qkv + ((size_t)b * SEQ + qt * QROWS) * N3 + h * HD;
#pragma unroll
    for (int j = 0; j < 8; j++) {
        int idx = tid + j * 128;
        int row = idx >> 3, c16 = idx & 7;
        cp_cg16(&Qs[row * AT_W + c16 * 4], qb + (size_t)row * N3 + c16 * 8);
    }

    const __half* kbase  = qkv + ((size_t)b * SEQ) * N3 + DM + h * HD;
    const __half* vtbase = vwT + ((size_t)b * DM + h * HD) * SEQ;
    const int*    mbase  = mkc + b * SEQ;

    attn_prefetch((unsigned*)sm_dyn, kbase, vtbase, mbase, 0, tid);
    asm volatile("cp.async.commit_group;" ::: "memory");
    attn_prefetch((unsigned*)sm_dyn + STAGE_W, kbase, vtbase, mbase, 1, tid);
    asm volatile("cp.async.commit_group;" ::: "memory");

    float m[2][2];
#pragma unroll
    for (int mi = 0; mi < 2; mi++) { m[mi][0] = -1e30f; m[mi][1] = -1e30f; }
    float o[2][8][4];
    float ol[2][4];
#pragma unroll
    for (int mi = 0; mi < 2; mi++) {
#pragma unroll
        for (int nf = 0; nf < 8; nf++)
#pragma unroll
            for (int e = 0; e < 4; e++) o[mi][nf][e] = 0.0f;
#pragma unroll
        for (int e = 0; e < 4; e++) ol[mi][e] = 0.0f;
    }

    const unsigned bones[2] = { ONES_H2, ONES_H2 };

    int st = 0;
    for (int kt = 0; kt < nt; kt++) {
        asm volatile("cp.async.wait_group 1;" ::: "memory");
        __syncthreads();
        if (kt + 2 < nt) {
            int j = st - 1; if (j < 0) j += NSTG;
            attn_prefetch((unsigned*)sm_dyn + j * STAGE_W,
                          kbase, vtbase, mbase, kt + 2, tid);
            asm volatile("cp.async.commit_group;" ::: "memory");
        } else {
            asm volatile("cp.async.commit_group;" ::: "memory");
        }
        const unsigned* Ks  = (const unsigned*)sm_dyn + st * STAGE_W;
        const unsigned* VTs = Ks + KTILE * AT_W;
        const int*      Mk  = (const int*)(VTs + KTILE * AT_W);
        const __half* Kh = (const __half*)Ks;
        const __half* Vh = (const __half*)VTs;
        if (++st == NSTG) st = 0;

        // ---- S = Q . K^T  (ldmatrix fragments) ----
        float s[2][8][4];
#pragma unroll
        for (int mi = 0; mi < 2; mi++)
#pragma unroll
            for (int nf = 0; nf < 8; nf++)
#pragma unroll
                for (int e = 0; e < 4; e++) s[mi][nf][e] = 0.0f;

#pragma unroll
        for (int kf = 0; kf < 4; kf++) {
            unsigned a0[4], a1[4];
            ldm4(a0[0], a0[1], a0[2], a0[3],
                 Qh + (qrow0 + rl) * 72 + kf * 16 + ch);
            ldm4(a1[0], a1[1], a1[2], a1[3],
                 Qh + (qrow0 + 16 + rl) * 72 + kf * 16 + ch);
            unsigned bk[8][2];
#pragma unroll
            for (int nj = 0; nj < 4; nj++) {
                unsigned r0, r1, r2, r3;
                ldm4(r0, r1, r2, r3, Kh + (nj * 16 + rl) * 72 + kf * 16 + ch);
                bk[2 * nj][0] = r0; bk[2 * nj + 1][0] = r1;
                bk[2 * nj][1] = r2; bk[2 * nj + 1][1] = r3;
            }
#pragma unroll
            for (int nf = 0; nf < 8; nf++) {
                mma_f16(s[0][nf], a0, bk[nf]);
                mma_f16(s[1][nf], a1, bk[nf]);
            }
        }

        // ---- mask + online softmax (exp2, f16x2; l via ones column) ----
        unsigned p01[2][8], p23[2][8];
#pragma unroll
        for (int mi = 0; mi < 2; mi++) {
            float mx0 = -1e30f, mx1 = -1e30f;
#pragma unroll
            for (int nf = 0; nf < 8; nf++) {
                float pen0 = Mk[nf * 8 + 2 * t]     ? 0.0f : 1e12f;
                float pen1 = Mk[nf * 8 + 2 * t + 1] ? 0.0f : 1e12f;
                s[mi][nf][0] -= pen0; s[mi][nf][1] -= pen1;
                s[mi][nf][2] -= pen0; s[mi][nf][3] -= pen1;
                mx0 = fmaxf(mx0, fmaxf(s[mi][nf][0], s[mi][nf][1]));
                mx1 = fmaxf(mx1, fmaxf(s[mi][nf][2], s[mi][nf][3]));
            }
            mx0 = fmaxf(mx0, __shfl_xor_sync(0xffffffffu, mx0, 1));
            mx0 = fmaxf(mx0, __shfl_xor_sync(0xffffffffu, mx0, 2));
            mx1 = fmaxf(mx1, __shfl_xor_sync(0xffffffffu, mx1, 1));
            mx1 = fmaxf(mx1, __shfl_xor_sync(0xffffffffu, mx1, 2));
            float mn0 = fmaxf(m[mi][0], mx0), mn1 = fmaxf(m[mi][1], mx1);
            float al0 = ex2f(m[mi][0] - mn0), al1 = ex2f(m[mi][1] - mn1);
            m[mi][0] = mn0; m[mi][1] = mn1;
#pragma unroll
            for (int nf = 0; nf < 8; nf++) {
                p01[mi][nf] = h2ex2(s[mi][nf][0] - mn0, s[mi][nf][1] - mn0);
                p23[mi][nf] = h2ex2(s[mi][nf][2] - mn1, s[mi][nf][3] - mn1);
            }
#pragma unroll
            for (int nf = 0; nf < 8; nf++) {
                o[mi][nf][0] *= al0; o[mi][nf][1] *= al0;
                o[mi][nf][2] *= al1; o[mi][nf][3] *= al1;
            }
            ol[mi][0] *= al0; ol[mi][1] *= al0;
            ol[mi][2] *= al1; ol[mi][3] *= al1;
        }

        // ---- O' += P . [V | 1]  (ldmatrix V fragments) ----
#pragma unroll
        for (int kf = 0; kf < 4; kf++) {
            unsigned af[2][4];
#pragma unroll
            for (int mi = 0; mi < 2; mi++) {
                af[mi][0] = p01[mi][2 * kf];
                af[mi][1] = p23[mi][2 * kf];
                af[mi][2] = p01[mi][2 * kf + 1];
                af[mi][3] = p23[mi][2 * kf + 1];
            }
            unsigned bv[8][2];
#pragma unroll
            for (int nj = 0; nj < 4; nj++) {
                unsigned r0, r1, r2, r3;
                ldm4(r0, r1, r2, r3, Vh + (nj * 16 + rl) * 72 + kf * 16 + ch);
                bv[2 * nj][0] = r0; bv[2 * nj + 1][0] = r1;
                bv[2 * nj][1] = r2; bv[2 * nj + 1][1] = r3;
            }
#pragma unroll
            for (int nf = 0; nf < 8; nf++) {
                mma_f16(o[0][nf], af[0], bv[nf]);
                mma_f16(o[1][nf], af[1], bv[nf]);
            }
            mma_f16(ol[0], af[0], bones);
            mma_f16(ol[1], af[1], bones);
        }
    }

    // ---- normalize; write ctx fp16 [token][c] ----
    __half* obase = ctx + ((size_t)b * SEQ + qt * QROWS + qrow0) * DM + h * HD;
#pragma unroll
    for (int mi = 0; mi < 2; mi++) {
        float inv0 = 1.0f / ol[mi][0], inv1 = 1.0f / ol[mi][2];
        __half* ob = obase + (size_t)(mi * 16) * DM;
#pragma unroll
        for (int nf = 0; nf < 8; nf++) {
            int col = nf * 8 + 2 * t;
            *(__half2*)&ob[(size_t)g * DM + col] =
                __floats2half2_rn(o[mi][nf][0] * inv0, o[mi][nf][1] * inv0);
            *(__half2*)&ob[(size_t)(g + 8) * DM + col] =
                __floats2half2_rn(o[mi][nf][2] * inv1, o[mi][nf][3] * inv1);
        }
    }
}

// ---------------------------------------------------------------------------
extern "C" void kernel_launch(void* const* d_in, const int* in_sizes, int n_in,
                              void* d_out, int out_size)
{
    const float* q    = (const float*)d_in[0];
    const float* k    = (const float*)d_in[1];
    const float* v    = (const float*)d_in[2];
    const int*   mask = (const int*)  d_in[3];
    const float* Wq   = (const float*)d_in[4];
    const float* bq   = (const float*)d_in[5];
    const float* Wk   = (const float*)d_in[6];
    const float* bk   = (const float*)d_in[7];
    const float* Wv   = (const float*)d_in[8];
    const float* bv   = (const float*)d_in[9];
    const float* Wo   = (const float*)d_in[10];
    const float* bo   = (const float*)d_in[11];
    float* out = (float*)d_out;

    void *pin, *pwT, *pqkv, *pvwT, *pctx, *pidx, *pmkc, *pntc;
    cudaGetSymbolAddress(&pin,  g_inh);
    cudaGetSymbolAddress(&pwT,  g_wT);
    cudaGetSymbolAddress(&pqkv, g_qkv);
    cudaGetSymbolAddress(&pvwT, g_vwT);
    cudaGetSymbolAddress(&pctx, g_ctx);
    cudaGetSymbolAddress(&pidx, g_idx);
    cudaGetSymbolAddress(&pmkc, g_mkc);
    cudaGetSymbolAddress(&pntc, g_ntc);

    __half* inh = (__half*)pin;
    __half* wT  = (__half*)pwT;
    __half* qkv = (__half*)pqkv;
    __half* vwT = (__half*)pvwT;
    __half* ctx = (__half*)pctx;
    int* idx = (int*)pidx;
    int* mkc = (int*)pmkc;
    int* ntc = (int*)pntc;

    cudaFuncSetAttribute(gemm_qkv,
                         cudaFuncAttributeMaxDynamicSharedMemorySize, GEMM_SMEM);
    cudaFuncSetAttribute(gemm_out,
                         cudaFuncAttributeMaxDynamicSharedMemorySize, GEMM_SMEM);
    cudaFuncSetAttribute(attn_mma,
                         cudaFuncAttributeMaxDynamicSharedMemorySize, ATTN_SMEM);

    // 1) prepass: converts, weight transposes, key compaction
    const int nBig = MROWS * DM / 4;
    to_f16_3<<<dim3(nBig / 256, 1, 3), 256>>>(
        (const float4*)q, (const float4*)k, (const float4*)v,
        (__half2*)inh, nBig);
    transp_w4<<<dim3(DM / 32, DM / 32, 4), dim3(32, 8)>>>(Wq, Wk, Wv, Wo, wT);
    compact_mask<<<NB, 1024>>>(mask, idx, mkc, ntc);

    // 2) grouped QKV projection (compacted K/V; V written transposed)
    gemm_qkv<<<dim3(DM / 128, MROWS / 128, 3), 256, GEMM_SMEM>>>(
        inh, wT, bq, bk, bv, qkv, vwT, idx, ntc);

    // 3) fused attention over compacted keys -> ctx (fp16), 3 CTAs/SM
    attn_mma<<<dim3(SEQ / QROWS, NH, NB), 128, ATTN_SMEM>>>(
        qkv, vwT, mkc, ntc, ctx);

    // 4) output projection (fp32 out)
    gemm_out<<<dim3(DM / 128, MROWS / 128), 256, GEMM_SMEM>>>(
        ctx, wT + 3 * (size_t)DM * DM, bo, out);
}

// round 17
// speedup vs baseline: 1.0289x; 1.0289x over previous
#include <cuda_runtime.h>
#include <cuda_fp16.h>
#include <math.h>
#include <cstdint>

#define SEQ 2048
#define DM 1024
#define NH 16
#define HD 64
#define NB 2
#define MROWS (NB * SEQ)   // 4096
#define N3 (3 * DM)        // 3072 (qkv buffer width)

// Q projection pre-scaled by 0.125*log2(e): softmax runs in exp2 domain.
#define QSCALE 0.18033688011112042f

// Scratch (__device__ globals; allocation-free rule).
__device__ __half g_inh[3 * MROWS * DM];  // fp16(q|k|v) inputs, tensor-major
__device__ __half g_wT[4 * DM * DM];      // fp16(Wq^T|Wk^T|Wv^T|Wo^T) [N][K]
__device__ __half g_qkv[MROWS * N3];      // fp16 proj: [token][Q|Kc|.]
__device__ __half g_vwT[NB * DM * SEQ];   // fp16(proj V)^T compacted [b][c][j]
__device__ __half g_ctx[MROWS * DM];      // fp16(attn out)  [token][c]
__device__ int    g_idx[NB * SEQ];        // compacted key token index (local)
__device__ int    g_mkc[NB * SEQ];        // compacted mask (1 valid, 0 pad)
__device__ int    g_ntc[NB];              // #64-key tiles per batch

__device__ __forceinline__ void mma_f16(float c[4], const unsigned a[4],
                                        const unsigned b[2]) {
    asm volatile(
        "mma.sync.aligned.m16n8k16.row.col.f32.f16.f16.f32 "
        "{%0,%1,%2,%3}, {%4,%5,%6,%7}, {%8,%9}, {%0,%1,%2,%3};\n"
        : "+f"(c[0]), "+f"(c[1]), "+f"(c[2]), "+f"(c[3])
        : "r"(a[0]), "r"(a[1]), "r"(a[2]), "r"(a[3]), "r"(b[0]), "r"(b[1]));
}

__device__ __forceinline__ unsigned h2ex2(float lo, float hi) {
    __half2 d = __floats2half2_rn(lo, hi);
    unsigned x = *(unsigned*)&d, r;
    asm("ex2.approx.f16x2 %0, %1;" : "=r"(r) : "r"(x));
    return r;
}
__device__ __forceinline__ float ex2f(float x) {
    float r;
    asm("ex2.approx.f32 %0, %1;" : "=f"(r) : "f"(x));
    return r;
}

__device__ __forceinline__ void cp_cg16(void* dst, const void* src) {
    unsigned u = (unsigned)__cvta_generic_to_shared(dst);
    asm volatile("cp.async.cg.shared.global [%0], [%1], 16;" :: "r"(u), "l"(src));
}

extern __shared__ float sm_dyn[];

// ---------------------------------------------------------------------------
// Fused prepass: z<3 -> fp16 convert of q/k/v; z in [3,7) -> weight transpose.
// All slices use 256-thread blocks; transpose slices use blocks [0,1024) only.
// ---------------------------------------------------------------------------
__global__ __launch_bounds__(256) void prep_all(
    const float4* __restrict__ q, const float4* __restrict__ k,
    const float4* __restrict__ v, __half2* __restrict__ outc, int n4,
    const float* __restrict__ w0, const float* __restrict__ w1,
    const float* __restrict__ w2, const float* __restrict__ w3,
    __half* __restrict__ outw)
{
    const int z = blockIdx.z;
    if (z < 3) {
        int i = blockIdx.x * 256 + threadIdx.x;
        const float4* in = (z == 0) ? q : (z == 1) ? k : v;
        __half2* o = outc + (size_t)z * (2 * (size_t)n4);
        if (i < n4) {
            float4 x = in[i];
            o[2 * i]     = __floats2half2_rn(x.x, x.y);
            o[2 * i + 1] = __floats2half2_rn(x.z, x.w);
        }
    } else {
        if (blockIdx.x >= 1024) return;
        __shared__ float t[32][33];
        const int wz = z - 3;
        const float* in = (wz == 0) ? w0 : (wz == 1) ? w1
                        : (wz == 2) ? w2 : w3;
        __half* o = outw + (size_t)wz * DM * DM;
        int tx = threadIdx.x & 31, ty = threadIdx.x >> 5;       // 32 x 8
        int bx = (blockIdx.x & 31) * 32, by = (blockIdx.x >> 5) * 32;
#pragma unroll
        for (int j = 0; j < 4; j++)
            t[ty + j * 8][tx] = in[(size_t)(by + ty + j * 8) * DM + bx + tx];
        __syncthreads();
#pragma unroll
        for (int j = 0; j < 4; j++)
            o[(size_t)(bx + ty + j * 8) * DM + by + tx] =
                __float2half_rn(t[tx][ty + j * 8]);
    }
}

// Order-preserving key compaction (masked keys have exactly 0 weight:
// exp(s - 1e12 - max) underflows to 0.0f in the fp32 reference).
__global__ __launch_bounds__(1024) void compact_mask(
    const int* __restrict__ vmask, int* __restrict__ idx,
    int* __restrict__ mkc, int* __restrict__ ntc)
{
    __shared__ int s[1024];
    __shared__ int cnt_s;
    const int b = blockIdx.x, t = threadIdx.x;
    const int* mb = vmask + b * SEQ;
    const int m0 = mb[2 * t] ? 1 : 0;
    const int m1 = mb[2 * t + 1] ? 1 : 0;
    const int p = m0 + m1;
    s[t] = p;
    __syncthreads();
    for (int off = 1; off < 1024; off <<= 1) {
        int v = s[t];
        if (t >= off) v += s[t - off];
        __syncthreads();
        s[t] = v;
        __syncthreads();
    }
    const int incl = s[t];
    if (t == 1023) cnt_s = incl;
    __syncthreads();
    const int cnt = cnt_s;
    idx[b * SEQ + t] = 0;
    idx[b * SEQ + t + 1024] = 0;
    mkc[b * SEQ + t] = (t < cnt) ? 1 : 0;
    mkc[b * SEQ + t + 1024] = (t + 1024 < cnt) ? 1 : 0;
    __syncthreads();
    const int e = incl - p;
    if (m0) idx[b * SEQ + e] = 2 * t;
    if (m1) idx[b * SEQ + e + m0] = 2 * t + 1;
    if (t == 0) ntc[b] = (cnt + 63) >> 6;
}

// ---------------------------------------------------------------------------
// GEMM tiles: 128x128 block, 256 threads, 8 warps x (64x32), m16n8k16,
// k-chunk 64 halves, 3-stage cp.async (wait_group 1), pitch 36 words.
// Scalar LDS fragment loads (measured faster than ldmatrix here: the loop is
// latency-bound and many independent LDS.32 hide it better).
// A-rows addressed through an smem token table (gather support).
// ---------------------------------------------------------------------------
#define GW 36
#define GEMM_STAGE (128 * GW)
#define GEMM_NSTG 3
#define GEMM_SMEM ((2 * GEMM_NSTG * GEMM_STAGE) * (int)sizeof(float))  // 110592

__device__ __forceinline__ void gemm_prefetch(
    unsigned* As, unsigned* Bs, const __half* A, const __half* WT,
    const int* __restrict__ stok,
    int K, int bn, int k0, int tid)
{
#pragma unroll
    for (int j = 0; j < 4; j++) {
        int idx = tid + j * 256;
        int row = idx >> 3;
        int c16 = idx & 7;
        cp_cg16(&As[row * GW + c16 * 4],
                A + (size_t)stok[row] * K + k0 + c16 * 8);
        cp_cg16(&Bs[row * GW + c16 * 4],
                WT + (size_t)(bn + row) * K + k0 + c16 * 8);
    }
}

__device__ __forceinline__ void gemm_mainloop(
    float acc[4][4][4], const __half* A, const __half* WT,
    const int* __restrict__ stok,
    int K, int bn, int tid, int wm, int wn, int g, int t)
{
    unsigned* As0 = (unsigned*)sm_dyn;
    unsigned* Bs0 = As0 + GEMM_NSTG * GEMM_STAGE;

    gemm_prefetch(As0, Bs0, A, WT, stok, K, bn, 0, tid);
    asm volatile("cp.async.commit_group;" ::: "memory");
    gemm_prefetch(As0 + GEMM_STAGE, Bs0 + GEMM_STAGE, A, WT, stok, K, bn, 64, tid);
    asm volatile("cp.async.commit_group;" ::: "memory");

    const int NKI = K / 64;
    for (int i = 0; i < NKI; i++) {
        asm volatile("cp.async.wait_group 1;" ::: "memory");
        __syncthreads();
        int pf = i + 2;
        if (pf < NKI) {
            int j = pf % GEMM_NSTG;
            gemm_prefetch(As0 + j * GEMM_STAGE, Bs0 + j * GEMM_STAGE,
                          A, WT, stok, K, bn, pf * 64, tid);
        }
        asm volatile("cp.async.commit_group;" ::: "memory");
        const int st = i % GEMM_NSTG;
        const unsigned* As = As0 + st * GEMM_STAGE;
        const unsigned* Bs = Bs0 + st * GEMM_STAGE;

#pragma unroll
        for (int kf = 0; kf < 4; kf++) {
            unsigned af[4][4], bf[4][2];
#pragma unroll
            for (int mi = 0; mi < 4; mi++) {
                int r = wm + mi * 16;
                af[mi][0] = As[(r + g)     * GW + kf * 8 + t];
                af[mi][1] = As[(r + g + 8) * GW + kf * 8 + t];
                af[mi][2] = As[(r + g)     * GW + kf * 8 + t + 4];
                af[mi][3] = As[(r + g + 8) * GW + kf * 8 + t + 4];
            }
#pragma unroll
            for (int ni = 0; ni < 4; ni++) {
                int c = wn + ni * 8;
                bf[ni][0] = Bs[(c + g) * GW + kf * 8 + t];
                bf[ni][1] = Bs[(c + g) * GW + kf * 8 + t + 4];
            }
#pragma unroll
            for (int mi = 0; mi < 4; mi++)
#pragma unroll
                for (int ni = 0; ni < 4; ni++)
                    mma_f16(acc[mi][ni], af[mi], bf[ni]);
        }
    }
}

// Grouped QKV projection. z=0: Q (scaled), all tokens. z=1: K compacted.
// z=2: V compacted -> vwT[b][c][j] transposed via smem restage.
__global__ __launch_bounds__(256, 2) void gemm_qkv(
    const __half* __restrict__ inh, const __half* __restrict__ wT,
    const float* __restrict__ bq, const float* __restrict__ bk,
    const float* __restrict__ bv, __half* __restrict__ qkv,
    __half* __restrict__ vwT,
    const int* __restrict__ idx, const int* __restrict__ ntc)
{
    __shared__ int stok[128];

    const int tid  = threadIdx.x;
    const int lane = tid & 31;
    const int warp = tid >> 5;
    const int g = lane >> 2, t = lane & 3;
    const int wm = (warp >> 2) * 64;
    const int wn = (warp & 3) * 32;
    const int bm = blockIdx.y * 128;
    const int bn = blockIdx.x * 128;
    const int z  = blockIdx.z;
    const int b  = bm >> 11;
    const int lm = bm & 2047;

    if (z > 0 && lm >= ntc[b] * 64) return;

    if (tid < 128)
        stok[tid] = (z == 0) ? (bm + tid)
                             : (b * SEQ + idx[b * SEQ + lm + tid]);
    __syncthreads();

    const __half* A  = inh + (size_t)z * MROWS * DM;
    const __half* WT = wT  + (size_t)z * DM * DM;
    const float* bias = (z == 0) ? bq : (z == 1) ? bk : bv;
    const float sc = (z == 0) ? QSCALE : 1.0f;

    float acc[4][4][4];
#pragma unroll
    for (int mi = 0; mi < 4; mi++)
#pragma unroll
        for (int ni = 0; ni < 4; ni++)
#pragma unroll
            for (int e = 0; e < 4; e++) acc[mi][ni][e] = 0.0f;

    gemm_mainloop(acc, A, WT, stok, DM, bn, tid, wm, wn, g, t);

    if (z < 2) {
#pragma unroll
        for (int mi = 0; mi < 4; mi++) {
            int r0 = bm + wm + mi * 16 + g;
#pragma unroll
            for (int ni = 0; ni < 4; ni++) {
                int cb = bn + wn + ni * 8 + 2 * t;
                float b0 = bias[cb], b1 = bias[cb + 1];
                float x00 = (acc[mi][ni][0] + b0) * sc;
                float x01 = (acc[mi][ni][1] + b1) * sc;
                float x10 = (acc[mi][ni][2] + b0) * sc;
                float x11 = (acc[mi][ni][3] + b1) * sc;
                __half* c0p = qkv + (size_t)r0 * N3 + z * DM + cb;
                *(__half2*)c0p = __floats2half2_rn(x00, x01);
                *(__half2*)(c0p + (size_t)8 * N3) = __floats2half2_rn(x10, x11);
            }
        }
    } else {
        // V: restage transposed through smem, write vwT[b][c][j] (compacted).
        __syncthreads();
        __half* ts = (__half*)sm_dyn;   // [128 c][136 tok-pitch]
#pragma unroll
        for (int mi = 0; mi < 4; mi++) {
            int tokl = wm + mi * 16 + g;
#pragma unroll
            for (int ni = 0; ni < 4; ni++) {
                int cl = wn + ni * 8 + 2 * t;
                float b0 = bias[bn + cl], b1 = bias[bn + cl + 1];
                ts[cl * 136 + tokl]           = __float2half_rn(acc[mi][ni][0] + b0);
                ts[(cl + 1) * 136 + tokl]     = __float2half_rn(acc[mi][ni][1] + b1);
                ts[cl * 136 + tokl + 8]       = __float2half_rn(acc[mi][ni][2] + b0);
                ts[(cl + 1) * 136 + tokl + 8] = __float2half_rn(acc[mi][ni][3] + b1);
            }
        }
        __syncthreads();
#pragma unroll
        for (int it = 0; it < 8; it++) {
            int idx2 = tid + it * 256;
            int cl = idx2 >> 4;
            int tk = (idx2 & 15) * 8;
            uint4 y = *(const uint4*)&ts[cl * 136 + tk];
            *(uint4*)&vwT[((size_t)b * DM + bn + cl) * SEQ + lm + tk] = y;
        }
    }
}

// Output projection: C(fp32) = ctx(fp16) @ Wo + bo.
__global__ __launch_bounds__(256, 2) void gemm_out(
    const __half* __restrict__ A, const __half* __restrict__ WT,
    const float* __restrict__ bias, float* __restrict__ C)
{
    __shared__ int stok[128];

    const int tid  = threadIdx.x;
    const int lane = tid & 31;
    const int warp = tid >> 5;
    const int g = lane >> 2, t = lane & 3;
    const int wm = (warp >> 2) * 64;
    const int wn = (warp & 3) * 32;
    const int bm = blockIdx.y * 128;
    const int bn = blockIdx.x * 128;

    if (tid < 128) stok[tid] = bm + tid;
    __syncthreads();

    float acc[4][4][4];
#pragma unroll
    for (int mi = 0; mi < 4; mi++)
#pragma unroll
        for (int ni = 0; ni < 4; ni++)
#pragma unroll
            for (int e = 0; e < 4; e++) acc[mi][ni][e] = 0.0f;

    gemm_mainloop(acc, A, WT, stok, DM, bn, tid, wm, wn, g, t);

#pragma unroll
    for (int mi = 0; mi < 4; mi++) {
        int r0 = bm + wm + mi * 16 + g;
#pragma unroll
        for (int ni = 0; ni < 4; ni++) {
            int cb = bn + wn + ni * 8 + 2 * t;
            float b0 = bias[cb], b1 = bias[cb + 1];
            *(float2*)&C[(size_t)r0 * DM + cb] =
                make_float2(acc[mi][ni][0] + b0, acc[mi][ni][1] + b1);
            *(float2*)&C[(size_t)(r0 + 8) * DM + cb] =
                make_float2(acc[mi][ni][2] + b0, acc[mi][ni][3] + b1);
        }
    }
}

// ---------------------------------------------------------------------------
// Flash-attention over COMPACTED keys (nt = ntc[b] tiles of 64).
// fp16 mma, exp2-domain softmax, ones-column l. 128 thr / 4 warps,
// QROWS=128 (32 rows/warp), 3 CTAs/SM.
// ---------------------------------------------------------------------------
#define QROWS 128
#define KTILE 64
#define NSTG 3
#define AT_W 36
#define STAGE_W (KTILE * AT_W * 2 + 64)
#define QS_W (QROWS * AT_W)
#define ATTN_SMEM ((NSTG * STAGE_W + QS_W) * (int)sizeof(float))  // 74496
#define ONES_H2 0x3C003C00u

__device__ __forceinline__ void attn_prefetch(
    unsigned* stage, const __half* kb, const __half* vtb, const int* mb,
    int kt, int tid)
{
    unsigned* Ks  = stage;
    unsigned* VTs = stage + KTILE * AT_W;
    unsigned* Mk  = VTs + KTILE * AT_W;
#pragma unroll
    for (int j = 0; j < 4; j++) {
        int idx = tid + j * 128;
        int row = idx >> 3;
        int c16 = idx & 7;
        cp_cg16(&Ks[row * AT_W + c16 * 4],
                kb + (size_t)(kt * KTILE + row) * N3 + c16 * 8);
        cp_cg16(&VTs[row * AT_W + c16 * 4],
                vtb + (size_t)row * SEQ + kt * KTILE + c16 * 8);
    }
    if (tid < 16) cp_cg16(&Mk[tid * 4], mb + kt * KTILE + tid * 4);
}

__global__ __launch_bounds__(128, 3) void attn_mma(
    const __half* __restrict__ qkv, const __half* __restrict__ vwT,
    const int* __restrict__ mkc, const int* __restrict__ ntc,
    __half* __restrict__ ctx)
{
    const int tid  = threadIdx.x;
    const int lane = tid & 31;
    const int warp = tid >> 5;
    const int g = lane >> 2, t = lane & 3;
    const int qrow0 = warp * 32;
    const int qt = blockIdx.x, h = blockIdx.y, b = blockIdx.z;
    const int nt = ntc[b];

    unsigned* Qs = (unsigned*)(sm_dyn + NSTG * STAGE_W);

    const __half* qb = qkv + ((size_t)b * SEQ + qt * QROWS) * N3 + h * HD;
#pragma unroll
    for (int j = 0; j < 8; j++) {
        int idx = tid + j * 128;
        int row = idx >> 3, c16 = idx & 7;
        cp_cg16(&Qs[row * AT_W + c16 * 4], qb + (size_t)row * N3 + c16 * 8);
    }

    const __half* kbase  = qkv + ((size_t)b * SEQ) * N3 + DM + h * HD;
    const __half* vtbase = vwT + ((size_t)b * DM + h * HD) * SEQ;
    const int*    mbase  = mkc + b * SEQ;

    attn_prefetch((unsigned*)sm_dyn, kbase, vtbase, mbase, 0, tid);
    asm volatile("cp.async.commit_group;" ::: "memory");
    attn_prefetch((unsigned*)sm_dyn + STAGE_W, kbase, vtbase, mbase, 1, tid);
    asm volatile("cp.async.commit_group;" ::: "memory");

    float m[2][2];
#pragma unroll
    for (int mi = 0; mi < 2; mi++) { m[mi][0] = -1e30f; m[mi][1] = -1e30f; }
    float o[2][8][4];
    float ol[2][4];
#pragma unroll
    for (int mi = 0; mi < 2; mi++) {
#pragma unroll
        for (int nf = 0; nf < 8; nf++)
#pragma unroll
            for (int e = 0; e < 4; e++) o[mi][nf][e] = 0.0f;
#pragma unroll
        for (int e = 0; e < 4; e++) ol[mi][e] = 0.0f;
    }

    const unsigned bones[2] = { ONES_H2, ONES_H2 };

    int st = 0;
    for (int kt = 0; kt < nt; kt++) {
        asm volatile("cp.async.wait_group 1;" ::: "memory");
        __syncthreads();
        if (kt + 2 < nt) {
            int j = st - 1; if (j < 0) j += NSTG;
            attn_prefetch((unsigned*)sm_dyn + j * STAGE_W,
                          kbase, vtbase, mbase, kt + 2, tid);
            asm volatile("cp.async.commit_group;" ::: "memory");
        } else {
            asm volatile("cp.async.commit_group;" ::: "memory");
        }
        const unsigned* Ks  = (const unsigned*)sm_dyn + st * STAGE_W;
        const unsigned* VTs = Ks + KTILE * AT_W;
        const int*      Mk  = (const int*)(VTs + KTILE * AT_W);
        if (++st == NSTG) st = 0;

        // ---- S = Q . K^T  (exp2-domain scores) ----
        float s[2][8][4];
#pragma unroll
        for (int mi = 0; mi < 2; mi++)
#pragma unroll
            for (int nf = 0; nf < 8; nf++)
#pragma unroll
                for (int e = 0; e < 4; e++) s[mi][nf][e] = 0.0f;

#pragma unroll
        for (int kf = 0; kf < 4; kf++) {
            unsigned a0[4], a1[4];
            a0[0] = Qs[(qrow0 + g)      * AT_W + kf * 8 + t];
            a0[1] = Qs[(qrow0 + g + 8)  * AT_W + kf * 8 + t];
            a0[2] = Qs[(qrow0 + g)      * AT_W + kf * 8 + t + 4];
            a0[3] = Qs[(qrow0 + g + 8)  * AT_W + kf * 8 + t + 4];
            a1[0] = Qs[(qrow0 + g + 16) * AT_W + kf * 8 + t];
            a1[1] = Qs[(qrow0 + g + 24) * AT_W + kf * 8 + t];
            a1[2] = Qs[(qrow0 + g + 16) * AT_W + kf * 8 + t + 4];
            a1[3] = Qs[(qrow0 + g + 24) * AT_W + kf * 8 + t + 4];
#pragma unroll
            for (int nf = 0; nf < 8; nf++) {
                unsigned bfr[2];
                bfr[0] = Ks[(nf * 8 + g) * AT_W + kf * 8 + t];
                bfr[1] = Ks[(nf * 8 + g) * AT_W + kf * 8 + t + 4];
                mma_f16(s[0][nf], a0, bfr);
                mma_f16(s[1][nf], a1, bfr);
            }
        }

        // ---- mask + online softmax (exp2, f16x2; l via ones column) ----
        unsigned p01[2][8], p23[2][8];
#pragma unroll
        for (int mi = 0; mi < 2; mi++) {
            float mx0 = -1e30f, mx1 = -1e30f;
#pragma unroll
            for (int nf = 0; nf < 8; nf++) {
                float pen0 = Mk[nf * 8 + 2 * t]     ? 0.0f : 1e12f;
                float pen1 = Mk[nf * 8 + 2 * t + 1] ? 0.0f : 1e12f;
                s[mi][nf][0] -= pen0; s[mi][nf][1] -= pen1;
                s[mi][nf][2] -= pen0; s[mi][nf][3] -= pen1;
                mx0 = fmaxf(mx0, fmaxf(s[mi][nf][0], s[mi][nf][1]));
                mx1 = fmaxf(mx1, fmaxf(s[mi][nf][2], s[mi][nf][3]));
            }
            mx0 = fmaxf(mx0, __shfl_xor_sync(0xffffffffu, mx0, 1));
            mx0 = fmaxf(mx0, __shfl_xor_sync(0xffffffffu, mx0, 2));
            mx1 = fmaxf(mx1, __shfl_xor_sync(0xffffffffu, mx1, 1));
            mx1 = fmaxf(mx1, __shfl_xor_sync(0xffffffffu, mx1, 2));
            float mn0 = fmaxf(m[mi][0], mx0), mn1 = fmaxf(m[mi][1], mx1);
            float al0 = ex2f(m[mi][0] - mn0), al1 = ex2f(m[mi][1] - mn1);
            m[mi][0] = mn0; m[mi][1] = mn1;
#pragma unroll
            for (int nf = 0; nf < 8; nf++) {
                p01[mi][nf] = h2ex2(s[mi][nf][0] - mn0, s[mi][nf][1] - mn0);
                p23[mi][nf] = h2ex2(s[mi][nf][2] - mn1, s[mi][nf][3] - mn1);
            }
#pragma unroll
            for (int nf = 0; nf < 8; nf++) {
                o[mi][nf][0] *= al0; o[mi][nf][1] *= al0;
                o[mi][nf][2] *= al1; o[mi][nf][3] *= al1;
            }
            ol[mi][0] *= al0; ol[mi][1] *= al0;
            ol[mi][2] *= al1; ol[mi][3] *= al1;
        }

        // ---- O' += P . [V | 1] ----
#pragma unroll
        for (int kf = 0; kf < 4; kf++) {
            unsigned af[2][4];
#pragma unroll
            for (int mi = 0; mi < 2; mi++) {
                af[mi][0] = p01[mi][2 * kf];
                af[mi][1] = p23[mi][2 * kf];
                af[mi][2] = p01[mi][2 * kf + 1];
                af[mi][3] = p23[mi][2 * kf + 1];
            }
#pragma unroll
            for (int nf = 0; nf < 8; nf++) {
                unsigned bfr[2];
                bfr[0] = VTs[(nf * 8 + g) * AT_W + kf * 8 + t];
                bfr[1] = VTs[(nf * 8 + g) * AT_W + kf * 8 + t + 4];
                mma_f16(o[0][nf], af[0], bfr);
                mma_f16(o[1][nf], af[1], bfr);
            }
            mma_f16(ol[0], af[0], bones);
            mma_f16(ol[1], af[1], bones);
        }
    }

    // ---- normalize; write ctx fp16 [token][c] ----
    __half* obase = ctx + ((size_t)b * SEQ + qt * QROWS + qrow0) * DM + h * HD;
#pragma unroll
    for (int mi = 0; mi < 2; mi++) {
        float inv0 = 1.0f / ol[mi][0], inv1 = 1.0f / ol[mi][2];
        __half* ob = obase + (size_t)(mi * 16) * DM;
#pragma unroll
        for (int nf = 0; nf < 8; nf++) {
            int col = nf * 8 + 2 * t;
            *(__half2*)&ob[(size_t)g * DM + col] =
                __floats2half2_rn(o[mi][nf][0] * inv0, o[mi][nf][1] * inv0);
            *(__half2*)&ob[(size_t)(g + 8) * DM + col] =
                __floats2half2_rn(o[mi][nf][2] * inv1, o[mi][nf][3] * inv1);
        }
    }
}

// ---------------------------------------------------------------------------
extern "C" void kernel_launch(void* const* d_in, const int* in_sizes, int n_in,
                              void* d_out, int out_size)
{
    const float* q    = (const float*)d_in[0];
    const float* k    = (const float*)d_in[1];
    const float* v    = (const float*)d_in[2];
    const int*   mask = (const int*)  d_in[3];
    const float* Wq   = (const float*)d_in[4];
    const float* bq   = (const float*)d_in[5];
    const float* Wk   = (const float*)d_in[6];
    const float* bk   = (const float*)d_in[7];
    const float* Wv   = (const float*)d_in[8];
    const float* bv   = (const float*)d_in[9];
    const float* Wo   = (const float*)d_in[10];
    const float* bo   = (const float*)d_in[11];
    float* out = (float*)d_out;

    void *pin, *pwT, *pqkv, *pvwT, *pctx, *pidx, *pmkc, *pntc;
    cudaGetSymbolAddress(&pin,  g_inh);
    cudaGetSymbolAddress(&pwT,  g_wT);
    cudaGetSymbolAddress(&pqkv, g_qkv);
    cudaGetSymbolAddress(&pvwT, g_vwT);
    cudaGetSymbolAddress(&pctx, g_ctx);
    cudaGetSymbolAddress(&pidx, g_idx);
    cudaGetSymbolAddress(&pmkc, g_mkc);
    cudaGetSymbolAddress(&pntc, g_ntc);

    __half* inh = (__half*)pin;
    __half* wT  = (__half*)pwT;
    __half* qkv = (__half*)pqkv;
    __half* vwT = (__half*)pvwT;
    __half* ctx = (__half*)pctx;
    int* idx = (int*)pidx;
    int* mkc = (int*)pmkc;
    int* ntc = (int*)pntc;

    cudaFuncSetAttribute(gemm_qkv,
                         cudaFuncAttributeMaxDynamicSharedMemorySize, GEMM_SMEM);
    cudaFuncSetAttribute(gemm_out,
                         cudaFuncAttributeMaxDynamicSharedMemorySize, GEMM_SMEM);
    cudaFuncSetAttribute(attn_mma,
                         cudaFuncAttributeMaxDynamicSharedMemorySize, ATTN_SMEM);

    // 1) fused prepass (converts + weight transposes in one launch) + compaction
    const int nBig = MROWS * DM / 4;   // 1048576/4 -> grid.x 4096
    prep_all<<<dim3(nBig / 256, 1, 7), 256>>>(
        (const float4*)q, (const float4*)k, (const float4*)v,
        (__half2*)inh, nBig, Wq, Wk, Wv, Wo, wT);
    compact_mask<<<NB, 1024>>>(mask, idx, mkc, ntc);

    // 2) grouped QKV projection (compacted K/V; V written transposed)
    gemm_qkv<<<dim3(DM / 128, MROWS / 128, 3), 256, GEMM_SMEM>>>(
        inh, wT, bq, bk, bv, qkv, vwT, idx, ntc);

    // 3) fused attention over compacted keys -> ctx (fp16), 3 CTAs/SM
    attn_mma<<<dim3(SEQ / QROWS, NH, NB), 128, ATTN_SMEM>>>(
        qkv, vwT, mkc, ntc, ctx);

    // 4) output projection (fp32 out)
    gemm_out<<<dim3(DM / 128, MROWS / 128), 256, GEMM_SMEM>>>(
        ctx, wT + 3 * (size_t)DM * DM, bo, out);
}